// round 15
// baseline (speedup 1.0000x reference)
#include <cuda_runtime.h>
#include <cuda_bf16.h>
#include <cstdint>

#define M_ 2048
#define D_ 900
#define H_ 150
#define K_ 50
#define NEG_ (-1000000000.0f)
#define NCH 29
#define DP 928
#define XB_ROWB 1856
#define GPC 5
#define SGRID ((M_ + GPC - 1) / GPC)   // 410

// score kernel smem (bytes): 8-stage ring, N-split CTA (80 cols)
#define NSTG 8
#define XWST 80
#define XWSZ (56 * 80)       // 4480
#define BSZ  (80 * 80)       // 6400
#define SXW 0                //  8*4480 = 35840
#define SB  35840            //  8*6400 = 51200 -> 87040
#define SPS 87040            //  5*80 f32 = 1600
#define SW2 88640            //  80 f32 = 320
#define SSZ 88960

// ---- scratch ----
__device__ float g_P[M_ * H_];
__device__ float g_Q[M_ * H_];
__device__ float g_ment[M_];
__device__ float g_sp[2][M_ * K_];
__device__ __align__(16) __nv_bfloat16 g_Xb[M_ * DP];
__device__ __align__(16) __nv_bfloat16 g_Wabm[480 * DP];
__device__ __align__(16) __nv_bfloat16 g_Wt[160 * DP];

// ============================ helpers ============================
__device__ __forceinline__ uint32_t smem_u32(const void* p) {
    uint32_t a;
    asm("{ .reg .u64 t; cvta.to.shared.u64 t, %1; cvt.u32.u64 %0, t; }" : "=r"(a) : "l"(p));
    return a;
}
__device__ __forceinline__ uint32_t bf2mul(uint32_t a, uint32_t b) {
    __nv_bfloat162 x, y, z;
    *(uint32_t*)&x = a; *(uint32_t*)&y = b;
    z = __hmul2(x, y);
    return *(uint32_t*)&z;
}
__device__ __forceinline__ void cp16(uint32_t dst, const void* src) {
    asm volatile("cp.async.cg.shared.global [%0], [%1], 16;" :: "r"(dst), "l"(src) : "memory");
}
#define CP_COMMIT() asm volatile("cp.async.commit_group;" ::: "memory")
#define CP_WAIT1()  asm volatile("cp.async.wait_group 1;" ::: "memory")
#define CVT_BF2(res, lo, hi) asm("cvt.rn.bf16x2.f32 %0, %1, %2;" : "=r"(res) : "f"(hi), "f"(lo))
#define LDSM_X4(r0, r1, r2, r3, addr) \
    asm volatile("ldmatrix.sync.aligned.m8n8.x4.shared.b16 {%0,%1,%2,%3}, [%4];" \
        : "=r"(r0), "=r"(r1), "=r"(r2), "=r"(r3) : "r"(addr))
#define LDSM_X2(r0, r1, addr) \
    asm volatile("ldmatrix.sync.aligned.m8n8.x2.shared.b16 {%0,%1}, [%2];" \
        : "=r"(r0), "=r"(r1) : "r"(addr))
#define MMA16816(c, a0, a1, a2, a3, b0, b1) \
    asm volatile("mma.sync.aligned.m16n8k16.row.col.f32.bf16.bf16.f32 " \
        "{%0,%1,%2,%3},{%4,%5,%6,%7},{%8,%9},{%0,%1,%2,%3};" \
        : "+f"((c)[0]), "+f"((c)[1]), "+f"((c)[2]), "+f"((c)[3]) \
        : "r"(a0), "r"(a1), "r"(a2), "r"(a3), "r"(b0), "r"(b1))

// ============================ prep X (8 bf16 per thread) ============================
#define N0 (M_ * DP)
#define X8 (N0 / 8)
__global__ __launch_bounds__(256) void prepx_kernel(const float* __restrict__ X)
{
    int t = blockIdx.x * 256 + threadIdx.x;
    if (t >= X8) return;
    int base = t * 8;
    int row = base / DP, d = base % DP;
    float v[8];
    if (d + 8 <= D_) {
        float4 a = __ldg((const float4*)(X + row * D_ + d));
        float4 b = __ldg((const float4*)(X + row * D_ + d + 4));
        v[0] = a.x; v[1] = a.y; v[2] = a.z; v[3] = a.w;
        v[4] = b.x; v[5] = b.y; v[6] = b.z; v[7] = b.w;
    } else {
        #pragma unroll
        for (int q = 0; q < 8; ++q)
            v[q] = (d + q < D_) ? __ldg(X + row * D_ + d + q) : 0.f;
    }
    uint4 o;
    CVT_BF2(o.x, v[0], v[1]);
    CVT_BF2(o.y, v[2], v[3]);
    CVT_BF2(o.z, v[4], v[5]);
    CVT_BF2(o.w, v[6], v[7]);
    *(uint4*)(g_Xb + base) = o;
}

// ============================ weight transpose (coalesced, smem tile) ============================
// grid (29, 5, 4), block (32, 8). z: 0=w1a, 1=w1b, 2=w1c(->g_Wt), 3=w1m.
__global__ __launch_bounds__(256) void wtrans_kernel(
    const float* __restrict__ w1p, const float* __restrict__ w1m)
{
    __shared__ float tile[32][33];
    const int z = blockIdx.z;
    const float* src = (z == 0) ? w1p : (z == 1) ? (w1p + D_ * H_)
                     : (z == 2) ? (w1p + 2 * D_ * H_) : w1m;
    __nv_bfloat16* dst = (z == 0) ? g_Wabm : (z == 1) ? (g_Wabm + 160 * DP)
                       : (z == 2) ? g_Wt : (g_Wabm + 320 * DP);
    const int d0 = blockIdx.x * 32, h0 = blockIdx.y * 32;
    const int tx = threadIdx.x, ty = threadIdx.y;

    #pragma unroll
    for (int i = 0; i < 4; ++i) {
        int d = d0 + ty + i * 8, h = h0 + tx;
        tile[ty + i * 8][tx] = (d < D_ && h < H_) ? __ldg(src + d * H_ + h) : 0.f;
    }
    __syncthreads();
    #pragma unroll
    for (int i = 0; i < 4; ++i) {
        int h = h0 + ty + i * 8, d = d0 + tx;
        if (h < 160 && d < DP)
            dst[h * DP + d] = __float2bfloat16(tile[tx][ty + i * 8]);
    }
}

// ============================ bf16 MMA GEMM for P/Q + fused ment (M=32 tiles) ============================
__global__ __launch_bounds__(256) void gemm_mma_kernel(
    const float* __restrict__ b1m, const float* __restrict__ w2m, const float* __restrict__ b2m)
{
    __shared__ __align__(16) unsigned char Asm[32 * 80];
    __shared__ __align__(16) unsigned char Bsm[160 * 80];
    __shared__ float mpart[4][32];

    const int tid = threadIdx.x;
    const int wid = tid >> 5;
    const int lane = tid & 31;
    const int row0 = blockIdx.x * 32;
    const int mat = blockIdx.y;
    const char* Bsrc = (const char*)(g_Wabm + mat * 160 * DP);

    const int mhalf = wid & 1;
    const int ngrp4 = wid >> 1;

    const uint32_t Ab = smem_u32(Asm);
    const uint32_t Bb = smem_u32(Bsm);
    const uint32_t a_off = Ab + (uint32_t)((mhalf * 16 + (lane & 15)) * 80 + ((lane >> 4) & 1) * 16);
    const uint32_t b_off = Bb + (uint32_t)((ngrp4 * 40 + (lane & 7)) * 80 + ((lane >> 3) & 1) * 16);

    float acc[5][4];
    #pragma unroll
    for (int nt = 0; nt < 5; ++nt)
        #pragma unroll
        for (int q = 0; q < 4; ++q) acc[nt][q] = 0.f;

    for (int c = 0; c < NCH; ++c) {
        if (tid < 128) {
            int r = tid >> 2, grp = tid & 3;
            uint4 v = __ldg((const uint4*)((const char*)g_Xb + (row0 + r) * XB_ROWB + c * 64 + grp * 16));
            *(uint4*)(Asm + r * 80 + grp * 16) = v;
        }
        for (int idx = tid; idx < 640; idx += 256) {
            int h = idx >> 2, grp = idx & 3;
            uint4 v = __ldg((const uint4*)(Bsrc + h * XB_ROWB + c * 64 + grp * 16));
            *(uint4*)(Bsm + h * 80 + grp * 16) = v;
        }
        __syncthreads();
        #pragma unroll
        for (int k16 = 0; k16 < 2; ++k16) {
            uint32_t a0, a1, a2, a3;
            LDSM_X4(a0, a1, a2, a3, a_off + k16 * 32);
            #pragma unroll
            for (int nt = 0; nt < 5; ++nt) {
                uint32_t b0, b1;
                LDSM_X2(b0, b1, b_off + nt * 640 + k16 * 32);
                MMA16816(acc[nt], a0, a1, a2, a3, b0, b1);
            }
        }
        __syncthreads();
    }

    const int g = lane >> 2, t = lane & 3;
    if (mat < 2) {
        float* dst = (mat == 0) ? g_P : g_Q;
        #pragma unroll
        for (int nt = 0; nt < 5; ++nt) {
            int h = ngrp4 * 40 + nt * 8 + t * 2;
            if (h < H_) {
                int ra = row0 + mhalf * 16 + g;
                dst[ra * H_ + h]           = acc[nt][0];
                dst[ra * H_ + h + 1]       = acc[nt][1];
                dst[(ra + 8) * H_ + h]     = acc[nt][2];
                dst[(ra + 8) * H_ + h + 1] = acc[nt][3];
            }
        }
    } else {
        float s0 = 0.f, s1 = 0.f;
        #pragma unroll
        for (int nt = 0; nt < 5; ++nt) {
            int h = ngrp4 * 40 + nt * 8 + t * 2;
            if (h < H_) {
                float ba = __ldg(b1m + h), bb = __ldg(b1m + h + 1);
                float wa = __ldg(w2m + h), wb = __ldg(w2m + h + 1);
                s0 += fmaxf(acc[nt][0] + ba, 0.f) * wa + fmaxf(acc[nt][1] + bb, 0.f) * wb;
                s1 += fmaxf(acc[nt][2] + ba, 0.f) * wa + fmaxf(acc[nt][3] + bb, 0.f) * wb;
            }
        }
        s0 += __shfl_xor_sync(0xffffffffu, s0, 1);
        s0 += __shfl_xor_sync(0xffffffffu, s0, 2);
        s1 += __shfl_xor_sync(0xffffffffu, s1, 1);
        s1 += __shfl_xor_sync(0xffffffffu, s1, 2);
        int rl = mhalf * 16 + g;
        if (t == 0) {
            mpart[ngrp4][rl] = s0;
            mpart[ngrp4][rl + 8] = s1;
        }
        __syncthreads();
        if (tid < 32)
            g_ment[row0 + tid] = mpart[0][tid] + mpart[1][tid] + mpart[2][tid] + mpart[3][tid]
                                 + __ldg(b2m);
    }
}

// ============================ score: N-split, 2 CTAs/SM, warp-staggered chunk order ============================
__global__ __launch_bounds__(256, 2) void score_mma_kernel(
    const float* __restrict__ b1p,
    const float* __restrict__ w2p)
{
    extern __shared__ __align__(16) unsigned char sm[];
    const int tid = threadIdx.x;
    const int wid = tid >> 5;
    const int lane = tid & 31;
    const int i0 = blockIdx.x * GPC;
    const int nh = blockIdx.y;

    float* Ps = (float*)(sm + SPS);      // [5][80]
    float* w2ps = (float*)(sm + SW2);    // [80]
    const uint32_t Sb = smem_u32(sm);

    // cp.async task mapping
    uint32_t dstA = 0; const char* srcA = nullptr;
    if (tid < 224) {
        int rr = tid >> 2, grp = tid & 3;
        int gr = i0 - K_ + rr;
        if (gr < 0) gr = 0; if (gr > M_ - 1) gr = M_ - 1;
        dstA = Sb + SXW + (uint32_t)(rr * XWST + grp * 16);
        srcA = (const char*)g_Xb + gr * XB_ROWB + grp * 16;
    }
    uint32_t dstB0, dstB1 = 0; const char* srcB0; const char* srcB1 = nullptr;
    {
        int hl = tid >> 2, grp = tid & 3;
        dstB0 = Sb + SB + (uint32_t)(hl * 80 + grp * 16);
        srcB0 = (const char*)g_Wt + (nh * 80 + hl) * XB_ROWB + grp * 16;
        if (tid < 64) {
            dstB1 = Sb + SB + (uint32_t)((64 + hl) * 80 + grp * 16);
            srcB1 = (const char*)g_Wt + (nh * 80 + 64 + hl) * XB_ROWB + grp * 16;
        }
    }

    // prologue: chunks 0,1 (group 1), 2,3 (group 2)
    #pragma unroll
    for (int cn = 0; cn < 2; ++cn) {
        uint32_t so = (uint32_t)cn;
        if (tid < 224) cp16(dstA + so * XWSZ, srcA + cn * 64);
        cp16(dstB0 + so * BSZ, srcB0 + cn * 64);
        if (tid < 64) cp16(dstB1 + so * BSZ, srcB1 + cn * 64);
    }
    CP_COMMIT();
    #pragma unroll
    for (int cn = 2; cn < 4; ++cn) {
        uint32_t so = (uint32_t)cn;
        if (tid < 224) cp16(dstA + so * XWSZ, srcA + cn * 64);
        cp16(dstB0 + so * BSZ, srcB0 + cn * 64);
        if (tid < 64) cp16(dstB1 + so * BSZ, srcB1 + cn * 64);
    }
    CP_COMMIT();

    // stage Ps / w2p
    for (int idx = tid; idx < GPC * 80; idx += 256) {
        int m = idx / 80, hl = idx % 80;
        int i = i0 + m; if (i > M_ - 1) i = M_ - 1;
        int h = nh * 80 + hl;
        Ps[idx] = (h < H_) ? (g_P[i * H_ + h] + b1p[h]) : 0.f;
    }
    for (int idx = tid; idx < 80; idx += 256) {
        int h = nh * 80 + idx;
        w2ps[idx] = (h < H_) ? w2p[h] : 0.f;
    }

    // per-lane ldmatrix A addresses (within-stage offsets)
    uint32_t axi[2], axj[2];
    {
        const int colh = ((lane >> 4) & 1) * 16;
        #pragma unroll
        for (int t = 0; t < 2; ++t) {
            int ra = wid * 32 + t * 16 + (lane & 15);
            int m = ra / 50;
            int k = ra - m * 50;
            if (m > 4) { m = 4; k = 49; }
            axi[t] = (uint32_t)((50 + m) * XWST + colh);
            axj[t] = (uint32_t)((m + k) * XWST + colh);
        }
    }
    const uint32_t b_off = (uint32_t)((((lane >> 4) & 1) * 8 + (lane & 7)) * 80
                                      + ((lane >> 3) & 1) * 16);

    float acc[2][10][4];
    #pragma unroll
    for (int t = 0; t < 2; ++t)
        #pragma unroll
        for (int nt = 0; nt < 10; ++nt)
            #pragma unroll
            for (int q = 0; q < 4; ++q) acc[t][nt][q] = 0.f;

    const int wodd = wid & 1;

    // main loop: 15 periods of 2 chunks; odd warps process the period's chunks in reverse
    for (int p = 0; p < 15; ++p) {
        CP_WAIT1();
        __syncthreads();
        #pragma unroll
        for (int q = 0; q < 2; ++q) {
            int cn = 2 * p + 4 + q;
            if (cn < NCH) {
                uint32_t stg = (uint32_t)(cn % NSTG);
                if (tid < 224) cp16(dstA + stg * XWSZ, srcA + cn * 64);
                cp16(dstB0 + stg * BSZ, srcB0 + cn * 64);
                if (tid < 64) cp16(dstB1 + stg * BSZ, srcB1 + cn * 64);
            }
        }
        CP_COMMIT();
        #pragma unroll
        for (int q = 0; q < 2; ++q) {
            int c = 2 * p + (wodd ? (1 - q) : q);
            if (c < NCH) {
                uint32_t stg = (uint32_t)(c % NSTG);
                const uint32_t xwb = Sb + SXW + stg * XWSZ;
                const uint32_t bbb = Sb + SB + stg * BSZ + b_off;
                #pragma unroll
                for (int k16 = 0; k16 < 2; ++k16) {
                    uint32_t a0[4], a1[4];
                    {
                        uint32_t xi0, xi1, xi2, xi3, xj0, xj1, xj2, xj3;
                        LDSM_X4(xi0, xi1, xi2, xi3, xwb + axi[0] + k16 * 32);
                        LDSM_X4(xj0, xj1, xj2, xj3, xwb + axj[0] + k16 * 32);
                        a0[0] = bf2mul(xi0, xj0); a0[1] = bf2mul(xi1, xj1);
                        a0[2] = bf2mul(xi2, xj2); a0[3] = bf2mul(xi3, xj3);
                        LDSM_X4(xi0, xi1, xi2, xi3, xwb + axi[1] + k16 * 32);
                        LDSM_X4(xj0, xj1, xj2, xj3, xwb + axj[1] + k16 * 32);
                        a1[0] = bf2mul(xi0, xj0); a1[1] = bf2mul(xi1, xj1);
                        a1[2] = bf2mul(xi2, xj2); a1[3] = bf2mul(xi3, xj3);
                    }
                    uint32_t bc0, bc1, bc2, bc3;
                    LDSM_X4(bc0, bc1, bc2, bc3, bbb + k16 * 32);
                    #pragma unroll
                    for (int pp = 0; pp < 5; ++pp) {
                        uint32_t bn0, bn1, bn2, bn3;
                        if (pp < 4) LDSM_X4(bn0, bn1, bn2, bn3, bbb + (pp + 1) * 1280 + k16 * 32);
                        MMA16816(acc[0][2 * pp],     a0[0], a0[1], a0[2], a0[3], bc0, bc1);
                        MMA16816(acc[0][2 * pp + 1], a0[0], a0[1], a0[2], a0[3], bc2, bc3);
                        MMA16816(acc[1][2 * pp],     a1[0], a1[1], a1[2], a1[3], bc0, bc1);
                        MMA16816(acc[1][2 * pp + 1], a1[0], a1[1], a1[2], a1[3], bc2, bc3);
                        if (pp < 4) { bc0 = bn0; bc1 = bn1; bc2 = bn2; bc3 = bn3; }
                    }
                }
            }
        }
    }

    // ---- epilogue: 80-col dot partials -> g_sp[nh] ----
    const int g = lane >> 2, t4 = lane & 3;
    #pragma unroll
    for (int t = 0; t < 2; ++t) {
        #pragma unroll
        for (int half = 0; half < 2; ++half) {
            const int r = wid * 32 + t * 16 + half * 8 + g;
            float p = 0.f;
            if (r < 250) {
                const int m = r / 50, k = r - m * 50;
                const int i = i0 + m;
                const int j = i0 + m + k - K_;
                if (i < M_ && j >= 0) {
                    const float* qrow = g_Q + j * H_;
                    const float* prow = Ps + m * 80;
                    #pragma unroll
                    for (int nt = 0; nt < 10; ++nt) {
                        int hl = nt * 8 + t4 * 2;
                        int h = nh * 80 + hl;
                        if (h < H_) {
                            float a = acc[t][nt][half * 2]     + prow[hl]     + __ldg(qrow + h);
                            float b = acc[t][nt][half * 2 + 1] + prow[hl + 1] + __ldg(qrow + h + 1);
                            p += fmaxf(a, 0.f) * w2ps[hl] + fmaxf(b, 0.f) * w2ps[hl + 1];
                        }
                    }
                }
                p += __shfl_xor_sync(0xffffffffu, p, 1);
                p += __shfl_xor_sync(0xffffffffu, p, 2);
                if (t4 == 0 && i < M_) g_sp[nh][i * K_ + k] = p;
            } else {
                p += __shfl_xor_sync(0xffffffffu, p, 1);
                p += __shfl_xor_sync(0xffffffffu, p, 2);
            }
        }
    }
}

// ============================ combine ============================
__global__ __launch_bounds__(256) void combine_kernel(
    const float* __restrict__ b2p, float* __restrict__ out)
{
    int idx = blockIdx.x * 256 + threadIdx.x;
    if (idx >= M_ * (K_ + 1)) return;
    int i = idx / (K_ + 1), k = idx % (K_ + 1);
    float v;
    if (k == K_) {
        v = 0.f;
    } else {
        int j = i + k - K_;
        v = (j >= 0)
            ? (g_ment[i] + g_ment[j] + __ldg(b2p) + g_sp[0][i * K_ + k] + g_sp[1][i * K_ + k])
            : NEG_;
    }
    out[idx] = v;
}

// ============================ launcher ============================
extern "C" void kernel_launch(void* const* d_in, const int* in_sizes, int n_in,
                              void* d_out, int out_size)
{
    const float* X   = (const float*)d_in[0];
    const float* w1m = (const float*)d_in[1];
    const float* b1m = (const float*)d_in[2];
    const float* w2m = (const float*)d_in[3];
    const float* b2m = (const float*)d_in[4];
    const float* w1p = (const float*)d_in[5];
    const float* b1p = (const float*)d_in[6];
    const float* w2p = (const float*)d_in[7];
    const float* b2p = (const float*)d_in[8];
    float* out = (float*)d_out;

    cudaFuncSetAttribute(score_mma_kernel,
                         cudaFuncAttributeMaxDynamicSharedMemorySize, SSZ);

    prepx_kernel<<<(X8 + 255) / 256, 256>>>(X);
    wtrans_kernel<<<dim3(29, 5, 4), dim3(32, 8)>>>(w1p, w1m);
    gemm_mma_kernel<<<dim3(64, 3), 256>>>(b1m, w2m, b2m);
    score_mma_kernel<<<dim3(SGRID, 2), 256, SSZ>>>(b1p, w2p);
    combine_kernel<<<(M_ * (K_ + 1) + 255) / 256, 256>>>(b2p, out);
}

// round 16
// speedup vs baseline: 1.0394x; 1.0394x over previous
#include <cuda_runtime.h>
#include <cuda_bf16.h>
#include <cstdint>

#define M_ 2048
#define D_ 900
#define H_ 150
#define K_ 50
#define NEG_ (-1000000000.0f)
#define NCH 29
#define DP 928
#define XB_ROWB 1856
#define GPC 5
#define SGRID ((M_ + GPC - 1) / GPC)   // 410

// score kernel smem (bytes): 8-stage ring, N-split CTA (80 cols)
#define NSTG 8
#define XWST 80
#define XWSZ (56 * 80)       // 4480
#define BSZ  (80 * 80)       // 6400
#define SXW 0                //  8*4480 = 35840
#define SB  35840            //  8*6400 = 51200 -> 87040
#define SPS 87040            //  5*80 f32 = 1600
#define SW2 88640            //  80 f32 = 320
#define SSZ 88960

// ---- scratch ----
__device__ float g_P[M_ * H_];
__device__ float g_Q[M_ * H_];
__device__ float g_ment[M_];
__device__ float g_sp[2][M_ * K_];
__device__ __align__(16) __nv_bfloat16 g_Xb[M_ * DP];
__device__ __align__(16) __nv_bfloat16 g_Wabm[480 * DP];
__device__ __align__(16) __nv_bfloat16 g_Wt[160 * DP];

// ============================ helpers ============================
__device__ __forceinline__ uint32_t smem_u32(const void* p) {
    uint32_t a;
    asm("{ .reg .u64 t; cvta.to.shared.u64 t, %1; cvt.u32.u64 %0, t; }" : "=r"(a) : "l"(p));
    return a;
}
__device__ __forceinline__ uint32_t bf2mul(uint32_t a, uint32_t b) {
    __nv_bfloat162 x, y, z;
    *(uint32_t*)&x = a; *(uint32_t*)&y = b;
    z = __hmul2(x, y);
    return *(uint32_t*)&z;
}
__device__ __forceinline__ void cp16(uint32_t dst, const void* src) {
    asm volatile("cp.async.cg.shared.global [%0], [%1], 16;" :: "r"(dst), "l"(src) : "memory");
}
#define CP_COMMIT() asm volatile("cp.async.commit_group;" ::: "memory")
#define CP_WAIT1()  asm volatile("cp.async.wait_group 1;" ::: "memory")
#define CVT_BF2(res, lo, hi) asm("cvt.rn.bf16x2.f32 %0, %1, %2;" : "=r"(res) : "f"(hi), "f"(lo))
#define LDSM_X4(r0, r1, r2, r3, addr) \
    asm volatile("ldmatrix.sync.aligned.m8n8.x4.shared.b16 {%0,%1,%2,%3}, [%4];" \
        : "=r"(r0), "=r"(r1), "=r"(r2), "=r"(r3) : "r"(addr))
#define LDSM_X2(r0, r1, addr) \
    asm volatile("ldmatrix.sync.aligned.m8n8.x2.shared.b16 {%0,%1}, [%2];" \
        : "=r"(r0), "=r"(r1) : "r"(addr))
#define MMA16816(c, a0, a1, a2, a3, b0, b1) \
    asm volatile("mma.sync.aligned.m16n8k16.row.col.f32.bf16.bf16.f32 " \
        "{%0,%1,%2,%3},{%4,%5,%6,%7},{%8,%9},{%0,%1,%2,%3};" \
        : "+f"((c)[0]), "+f"((c)[1]), "+f"((c)[2]), "+f"((c)[3]) \
        : "r"(a0), "r"(a1), "r"(a2), "r"(a3), "r"(b0), "r"(b1))

// ============================ prep X (8 bf16 per thread) ============================
#define N0 (M_ * DP)
#define X8 (N0 / 8)
__global__ __launch_bounds__(256) void prepx_kernel(const float* __restrict__ X)
{
    int t = blockIdx.x * 256 + threadIdx.x;
    if (t >= X8) return;
    int base = t * 8;
    int row = base / DP, d = base % DP;
    float v[8];
    if (d + 8 <= D_) {
        float4 a = __ldg((const float4*)(X + row * D_ + d));
        float4 b = __ldg((const float4*)(X + row * D_ + d + 4));
        v[0] = a.x; v[1] = a.y; v[2] = a.z; v[3] = a.w;
        v[4] = b.x; v[5] = b.y; v[6] = b.z; v[7] = b.w;
    } else {
        #pragma unroll
        for (int q = 0; q < 8; ++q)
            v[q] = (d + q < D_) ? __ldg(X + row * D_ + d + q) : 0.f;
    }
    uint4 o;
    CVT_BF2(o.x, v[0], v[1]);
    CVT_BF2(o.y, v[2], v[3]);
    CVT_BF2(o.z, v[4], v[5]);
    CVT_BF2(o.w, v[6], v[7]);
    *(uint4*)(g_Xb + base) = o;
}

// ============================ weight transpose (coalesced, smem tile) ============================
// grid (29, 5, 4), block (32, 8). z: 0=w1a, 1=w1b, 2=w1c(->g_Wt), 3=w1m.
__global__ __launch_bounds__(256) void wtrans_kernel(
    const float* __restrict__ w1p, const float* __restrict__ w1m)
{
    __shared__ float tile[32][33];
    const int z = blockIdx.z;
    const float* src = (z == 0) ? w1p : (z == 1) ? (w1p + D_ * H_)
                     : (z == 2) ? (w1p + 2 * D_ * H_) : w1m;
    __nv_bfloat16* dst = (z == 0) ? g_Wabm : (z == 1) ? (g_Wabm + 160 * DP)
                       : (z == 2) ? g_Wt : (g_Wabm + 320 * DP);
    const int d0 = blockIdx.x * 32, h0 = blockIdx.y * 32;
    const int tx = threadIdx.x, ty = threadIdx.y;

    #pragma unroll
    for (int i = 0; i < 4; ++i) {
        int d = d0 + ty + i * 8, h = h0 + tx;
        tile[ty + i * 8][tx] = (d < D_ && h < H_) ? __ldg(src + d * H_ + h) : 0.f;
    }
    __syncthreads();
    #pragma unroll
    for (int i = 0; i < 4; ++i) {
        int h = h0 + ty + i * 8, d = d0 + tx;
        if (h < 160 && d < DP)
            dst[h * DP + d] = __float2bfloat16(tile[tx][ty + i * 8]);
    }
}

// ============================ bf16 MMA GEMM for P/Q + fused ment (M=32 tiles) ============================
__global__ __launch_bounds__(256) void gemm_mma_kernel(
    const float* __restrict__ b1m, const float* __restrict__ w2m, const float* __restrict__ b2m)
{
    __shared__ __align__(16) unsigned char Asm[32 * 80];
    __shared__ __align__(16) unsigned char Bsm[160 * 80];
    __shared__ float mpart[4][32];

    const int tid = threadIdx.x;
    const int wid = tid >> 5;
    const int lane = tid & 31;
    const int row0 = blockIdx.x * 32;
    const int mat = blockIdx.y;
    const char* Bsrc = (const char*)(g_Wabm + mat * 160 * DP);

    const int mhalf = wid & 1;
    const int ngrp4 = wid >> 1;

    const uint32_t Ab = smem_u32(Asm);
    const uint32_t Bb = smem_u32(Bsm);
    const uint32_t a_off = Ab + (uint32_t)((mhalf * 16 + (lane & 15)) * 80 + ((lane >> 4) & 1) * 16);
    const uint32_t b_off = Bb + (uint32_t)((ngrp4 * 40 + (lane & 7)) * 80 + ((lane >> 3) & 1) * 16);

    float acc[5][4];
    #pragma unroll
    for (int nt = 0; nt < 5; ++nt)
        #pragma unroll
        for (int q = 0; q < 4; ++q) acc[nt][q] = 0.f;

    for (int c = 0; c < NCH; ++c) {
        if (tid < 128) {
            int r = tid >> 2, grp = tid & 3;
            uint4 v = __ldg((const uint4*)((const char*)g_Xb + (row0 + r) * XB_ROWB + c * 64 + grp * 16));
            *(uint4*)(Asm + r * 80 + grp * 16) = v;
        }
        for (int idx = tid; idx < 640; idx += 256) {
            int h = idx >> 2, grp = idx & 3;
            uint4 v = __ldg((const uint4*)(Bsrc + h * XB_ROWB + c * 64 + grp * 16));
            *(uint4*)(Bsm + h * 80 + grp * 16) = v;
        }
        __syncthreads();
        #pragma unroll
        for (int k16 = 0; k16 < 2; ++k16) {
            uint32_t a0, a1, a2, a3;
            LDSM_X4(a0, a1, a2, a3, a_off + k16 * 32);
            #pragma unroll
            for (int nt = 0; nt < 5; ++nt) {
                uint32_t b0, b1;
                LDSM_X2(b0, b1, b_off + nt * 640 + k16 * 32);
                MMA16816(acc[nt], a0, a1, a2, a3, b0, b1);
            }
        }
        __syncthreads();
    }

    const int g = lane >> 2, t = lane & 3;
    if (mat < 2) {
        float* dst = (mat == 0) ? g_P : g_Q;
        #pragma unroll
        for (int nt = 0; nt < 5; ++nt) {
            int h = ngrp4 * 40 + nt * 8 + t * 2;
            if (h < H_) {
                int ra = row0 + mhalf * 16 + g;
                dst[ra * H_ + h]           = acc[nt][0];
                dst[ra * H_ + h + 1]       = acc[nt][1];
                dst[(ra + 8) * H_ + h]     = acc[nt][2];
                dst[(ra + 8) * H_ + h + 1] = acc[nt][3];
            }
        }
    } else {
        float s0 = 0.f, s1 = 0.f;
        #pragma unroll
        for (int nt = 0; nt < 5; ++nt) {
            int h = ngrp4 * 40 + nt * 8 + t * 2;
            if (h < H_) {
                float ba = __ldg(b1m + h), bb = __ldg(b1m + h + 1);
                float wa = __ldg(w2m + h), wb = __ldg(w2m + h + 1);
                s0 += fmaxf(acc[nt][0] + ba, 0.f) * wa + fmaxf(acc[nt][1] + bb, 0.f) * wb;
                s1 += fmaxf(acc[nt][2] + ba, 0.f) * wa + fmaxf(acc[nt][3] + bb, 0.f) * wb;
            }
        }
        s0 += __shfl_xor_sync(0xffffffffu, s0, 1);
        s0 += __shfl_xor_sync(0xffffffffu, s0, 2);
        s1 += __shfl_xor_sync(0xffffffffu, s1, 1);
        s1 += __shfl_xor_sync(0xffffffffu, s1, 2);
        int rl = mhalf * 16 + g;
        if (t == 0) {
            mpart[ngrp4][rl] = s0;
            mpart[ngrp4][rl + 8] = s1;
        }
        __syncthreads();
        if (tid < 32)
            g_ment[row0 + tid] = mpart[0][tid] + mpart[1][tid] + mpart[2][tid] + mpart[3][tid]
                                 + __ldg(b2m);
    }
}

// ============================ score: N-split, 2 CTAs/SM, 8-stage ring (round-14 mainloop) ============================
__global__ __launch_bounds__(256, 2) void score_mma_kernel(
    const float* __restrict__ b1p,
    const float* __restrict__ w2p)
{
    extern __shared__ __align__(16) unsigned char sm[];
    const int tid = threadIdx.x;
    const int wid = tid >> 5;
    const int lane = tid & 31;
    const int i0 = blockIdx.x * GPC;
    const int nh = blockIdx.y;

    float* Ps = (float*)(sm + SPS);      // [5][80]
    float* w2ps = (float*)(sm + SW2);    // [80]
    const uint32_t Sb = smem_u32(sm);

    // cp.async task mapping
    uint32_t dstA = 0; const char* srcA = nullptr;
    if (tid < 224) {
        int rr = tid >> 2, grp = tid & 3;
        int gr = i0 - K_ + rr;
        if (gr < 0) gr = 0; if (gr > M_ - 1) gr = M_ - 1;
        dstA = Sb + SXW + (uint32_t)(rr * XWST + grp * 16);
        srcA = (const char*)g_Xb + gr * XB_ROWB + grp * 16;
    }
    uint32_t dstB0, dstB1 = 0; const char* srcB0; const char* srcB1 = nullptr;
    {
        int hl = tid >> 2, grp = tid & 3;
        dstB0 = Sb + SB + (uint32_t)(hl * 80 + grp * 16);
        srcB0 = (const char*)g_Wt + (nh * 80 + hl) * XB_ROWB + grp * 16;
        if (tid < 64) {
            dstB1 = Sb + SB + (uint32_t)((64 + hl) * 80 + grp * 16);
            srcB1 = (const char*)g_Wt + (nh * 80 + 64 + hl) * XB_ROWB + grp * 16;
        }
    }

    // prologue: chunks 0,1 (group 1), 2,3 (group 2)
    #pragma unroll
    for (int cn = 0; cn < 2; ++cn) {
        uint32_t so = (uint32_t)cn;
        if (tid < 224) cp16(dstA + so * XWSZ, srcA + cn * 64);
        cp16(dstB0 + so * BSZ, srcB0 + cn * 64);
        if (tid < 64) cp16(dstB1 + so * BSZ, srcB1 + cn * 64);
    }
    CP_COMMIT();
    #pragma unroll
    for (int cn = 2; cn < 4; ++cn) {
        uint32_t so = (uint32_t)cn;
        if (tid < 224) cp16(dstA + so * XWSZ, srcA + cn * 64);
        cp16(dstB0 + so * BSZ, srcB0 + cn * 64);
        if (tid < 64) cp16(dstB1 + so * BSZ, srcB1 + cn * 64);
    }
    CP_COMMIT();

    // stage Ps / w2p
    for (int idx = tid; idx < GPC * 80; idx += 256) {
        int m = idx / 80, hl = idx % 80;
        int i = i0 + m; if (i > M_ - 1) i = M_ - 1;
        int h = nh * 80 + hl;
        Ps[idx] = (h < H_) ? (g_P[i * H_ + h] + b1p[h]) : 0.f;
    }
    for (int idx = tid; idx < 80; idx += 256) {
        int h = nh * 80 + idx;
        w2ps[idx] = (h < H_) ? w2p[h] : 0.f;
    }

    // per-lane ldmatrix A addresses (within-stage offsets)
    uint32_t axi[2], axj[2];
    {
        const int colh = ((lane >> 4) & 1) * 16;
        #pragma unroll
        for (int t = 0; t < 2; ++t) {
            int ra = wid * 32 + t * 16 + (lane & 15);
            int m = ra / 50;
            int k = ra - m * 50;
            if (m > 4) { m = 4; k = 49; }
            axi[t] = (uint32_t)((50 + m) * XWST + colh);
            axj[t] = (uint32_t)((m + k) * XWST + colh);
        }
    }
    const uint32_t b_off = (uint32_t)((((lane >> 4) & 1) * 8 + (lane & 7)) * 80
                                      + ((lane >> 3) & 1) * 16);

    float acc[2][10][4];
    #pragma unroll
    for (int t = 0; t < 2; ++t)
        #pragma unroll
        for (int nt = 0; nt < 10; ++nt)
            #pragma unroll
            for (int q = 0; q < 4; ++q) acc[t][nt][q] = 0.f;

    // main loop: 15 periods of 2 chunks (program order, no stagger)
    for (int p = 0; p < 15; ++p) {
        CP_WAIT1();
        __syncthreads();
        #pragma unroll
        for (int q = 0; q < 2; ++q) {
            int cn = 2 * p + 4 + q;
            if (cn < NCH) {
                uint32_t stg = (uint32_t)(cn % NSTG);
                if (tid < 224) cp16(dstA + stg * XWSZ, srcA + cn * 64);
                cp16(dstB0 + stg * BSZ, srcB0 + cn * 64);
                if (tid < 64) cp16(dstB1 + stg * BSZ, srcB1 + cn * 64);
            }
        }
        CP_COMMIT();
        #pragma unroll
        for (int q = 0; q < 2; ++q) {
            int c = 2 * p + q;
            if (c < NCH) {
                uint32_t stg = (uint32_t)(c % NSTG);
                const uint32_t xwb = Sb + SXW + stg * XWSZ;
                const uint32_t bbb = Sb + SB + stg * BSZ + b_off;
                #pragma unroll
                for (int k16 = 0; k16 < 2; ++k16) {
                    uint32_t a0[4], a1[4];
                    {
                        uint32_t xi0, xi1, xi2, xi3, xj0, xj1, xj2, xj3;
                        LDSM_X4(xi0, xi1, xi2, xi3, xwb + axi[0] + k16 * 32);
                        LDSM_X4(xj0, xj1, xj2, xj3, xwb + axj[0] + k16 * 32);
                        a0[0] = bf2mul(xi0, xj0); a0[1] = bf2mul(xi1, xj1);
                        a0[2] = bf2mul(xi2, xj2); a0[3] = bf2mul(xi3, xj3);
                        LDSM_X4(xi0, xi1, xi2, xi3, xwb + axi[1] + k16 * 32);
                        LDSM_X4(xj0, xj1, xj2, xj3, xwb + axj[1] + k16 * 32);
                        a1[0] = bf2mul(xi0, xj0); a1[1] = bf2mul(xi1, xj1);
                        a1[2] = bf2mul(xi2, xj2); a1[3] = bf2mul(xi3, xj3);
                    }
                    uint32_t bc0, bc1, bc2, bc3;
                    LDSM_X4(bc0, bc1, bc2, bc3, bbb + k16 * 32);
                    #pragma unroll
                    for (int pp = 0; pp < 5; ++pp) {
                        uint32_t bn0, bn1, bn2, bn3;
                        if (pp < 4) LDSM_X4(bn0, bn1, bn2, bn3, bbb + (pp + 1) * 1280 + k16 * 32);
                        MMA16816(acc[0][2 * pp],     a0[0], a0[1], a0[2], a0[3], bc0, bc1);
                        MMA16816(acc[0][2 * pp + 1], a0[0], a0[1], a0[2], a0[3], bc2, bc3);
                        MMA16816(acc[1][2 * pp],     a1[0], a1[1], a1[2], a1[3], bc0, bc1);
                        MMA16816(acc[1][2 * pp + 1], a1[0], a1[1], a1[2], a1[3], bc2, bc3);
                        if (pp < 4) { bc0 = bn0; bc1 = bn1; bc2 = bn2; bc3 = bn3; }
                    }
                }
            }
        }
    }

    // ---- epilogue: 80-col dot partials -> g_sp[nh] ----
    const int g = lane >> 2, t4 = lane & 3;
    #pragma unroll
    for (int t = 0; t < 2; ++t) {
        #pragma unroll
        for (int half = 0; half < 2; ++half) {
            const int r = wid * 32 + t * 16 + half * 8 + g;
            float p = 0.f;
            if (r < 250) {
                const int m = r / 50, k = r - m * 50;
                const int i = i0 + m;
                const int j = i0 + m + k - K_;
                if (i < M_ && j >= 0) {
                    const float* qrow = g_Q + j * H_;
                    const float* prow = Ps + m * 80;
                    #pragma unroll
                    for (int nt = 0; nt < 10; ++nt) {
                        int hl = nt * 8 + t4 * 2;
                        int h = nh * 80 + hl;
                        if (h < H_) {
                            float a = acc[t][nt][half * 2]     + prow[hl]     + __ldg(qrow + h);
                            float b = acc[t][nt][half * 2 + 1] + prow[hl + 1] + __ldg(qrow + h + 1);
                            p += fmaxf(a, 0.f) * w2ps[hl] + fmaxf(b, 0.f) * w2ps[hl + 1];
                        }
                    }
                }
                p += __shfl_xor_sync(0xffffffffu, p, 1);
                p += __shfl_xor_sync(0xffffffffu, p, 2);
                if (t4 == 0 && i < M_) g_sp[nh][i * K_ + k] = p;
            } else {
                p += __shfl_xor_sync(0xffffffffu, p, 1);
                p += __shfl_xor_sync(0xffffffffu, p, 2);
            }
        }
    }
}

// ============================ combine ============================
__global__ __launch_bounds__(256) void combine_kernel(
    const float* __restrict__ b2p, float* __restrict__ out)
{
    int idx = blockIdx.x * 256 + threadIdx.x;
    if (idx >= M_ * (K_ + 1)) return;
    int i = idx / (K_ + 1), k = idx % (K_ + 1);
    float v;
    if (k == K_) {
        v = 0.f;
    } else {
        int j = i + k - K_;
        v = (j >= 0)
            ? (g_ment[i] + g_ment[j] + __ldg(b2p) + g_sp[0][i * K_ + k] + g_sp[1][i * K_ + k])
            : NEG_;
    }
    out[idx] = v;
}

// ============================ launcher ============================
extern "C" void kernel_launch(void* const* d_in, const int* in_sizes, int n_in,
                              void* d_out, int out_size)
{
    const float* X   = (const float*)d_in[0];
    const float* w1m = (const float*)d_in[1];
    const float* b1m = (const float*)d_in[2];
    const float* w2m = (const float*)d_in[3];
    const float* b2m = (const float*)d_in[4];
    const float* w1p = (const float*)d_in[5];
    const float* b1p = (const float*)d_in[6];
    const float* w2p = (const float*)d_in[7];
    const float* b2p = (const float*)d_in[8];
    float* out = (float*)d_out;

    cudaFuncSetAttribute(score_mma_kernel,
                         cudaFuncAttributeMaxDynamicSharedMemorySize, SSZ);

    prepx_kernel<<<(X8 + 255) / 256, 256>>>(X);
    wtrans_kernel<<<dim3(29, 5, 4), dim3(32, 8)>>>(w1p, w1m);
    gemm_mma_kernel<<<dim3(64, 3), 256>>>(b1m, w2m, b2m);
    score_mma_kernel<<<dim3(SGRID, 2), 256, SSZ>>>(b1p, w2p);
    combine_kernel<<<(M_ * (K_ + 1) + 255) / 256, 256>>>(b2p, out);
}